// round 14
// baseline (speedup 1.0000x reference)
#include <cuda_runtime.h>
#include <cuda_bf16.h>
#include <cstdint>

#define C2    240
#define MPAD  256
#define LDIM  1024
#define EDIM  8192
#define BM    128
#define BN    64
#define BK    64
#define KSPLIT 8
#define KSLICE (EDIM / KSPLIT)       // 1024
#define NCHUNK (KSLICE / BK)         // 16
#define TILE_W_BYTES (128 * 128)     // 128 rows x 64 bf16 = 16384 B
#define TILE_A_BYTES (64 * 128)      // 64 rows x 64 bf16 = 8192 B
#define STAGE_BYTES (2 * TILE_W_BYTES + 2 * TILE_A_BYTES)   // 49152
#define SMEM_REQ (1024 + 2 * STAGE_BYTES)                   // ~99 KB
#define NCG    16                    // c-groups in reduce stage 1
#define CPG    (C2 / NCG)            // 15 c-rows per group

// ---------------- device scratch (16B aligned for cp.async) ----------------
__device__ __align__(256) __nv_bfloat16 g_Whi[MPAD * EDIM];
__device__ __align__(256) __nv_bfloat16 g_Wlo[MPAD * EDIM];
__device__ __align__(256) __nv_bfloat16 g_Ahi[LDIM * EDIM];   // transposed [l, k]
__device__ __align__(256) __nv_bfloat16 g_Alo[LDIM * EDIM];
__device__ float g_partial[KSPLIT * MPAD * LDIM];   // 8 MB
__device__ float g_red1[NCG * LDIM];
__device__ float g_red2[NCG * LDIM];
__device__ float g_colsum[LDIM];

// ---------------- helpers ----------------
__device__ __forceinline__ uint32_t smem_u32(const void* p) {
    uint32_t a;
    asm("{ .reg .u64 t; cvta.to.shared.u64 t, %1; cvt.u32.u64 %0, t; }" : "=r"(a) : "l"(p));
    return a;
}
#define SW128(o) ((o) ^ (((o) >> 3) & 0x70))

#define CP_ASYNC16(dst, src) \
    asm volatile("cp.async.cg.shared.global [%0], [%1], 16;" :: "r"(dst), "l"(src))
#define CP_COMMIT() asm volatile("cp.async.commit_group;" ::: "memory")
#define CP_WAIT(n)  asm volatile("cp.async.wait_group %0;" :: "n"(n) : "memory")

#define LDM_X4(r0, r1, r2, r3, a) \
    asm volatile("ldmatrix.sync.aligned.m8n8.x4.shared.b16 {%0,%1,%2,%3}, [%4];" \
                 : "=r"(r0), "=r"(r1), "=r"(r2), "=r"(r3) : "r"(a))

__device__ __forceinline__ void mma16816(float* d, const uint32_t* a, const uint32_t* b) {
    asm volatile(
        "mma.sync.aligned.m16n8k16.row.col.f32.bf16.bf16.f32 "
        "{%0,%1,%2,%3}, {%4,%5,%6,%7}, {%8,%9}, {%0,%1,%2,%3};"
        : "+f"(d[0]), "+f"(d[1]), "+f"(d[2]), "+f"(d[3])
        : "r"(a[0]), "r"(a[1]), "r"(a[2]), "r"(a[3]), "r"(b[0]), "r"(b[1]));
}

// ---------------------------------------------------------------------------
// Kernel: convert W fp32 -> bf16 hi/lo, pad rows [240,256) with zeros
// ---------------------------------------------------------------------------
__global__ __launch_bounds__(256)
void conv_w_kernel(const float* __restrict__ W) {
    int gid = blockIdx.x * 256 + threadIdx.x;
    int idx4 = gid * 4;
    int row = idx4 >> 13;
    int col = idx4 & (EDIM - 1);
    float4 v = make_float4(0.f, 0.f, 0.f, 0.f);
    if (row < C2) v = *(const float4*)(W + (size_t)row * EDIM + col);
    float vv[4] = {v.x, v.y, v.z, v.w};
    __nv_bfloat16 hi[4], lo[4];
    #pragma unroll
    for (int i = 0; i < 4; i++) {
        hi[i] = __float2bfloat16(vv[i]);
        lo[i] = __float2bfloat16(vv[i] - __bfloat162float(hi[i]));
    }
    size_t o = (size_t)row * EDIM + col;
    *(__nv_bfloat162*)(g_Whi + o)     = __nv_bfloat162{hi[0], hi[1]};
    *(__nv_bfloat162*)(g_Whi + o + 2) = __nv_bfloat162{hi[2], hi[3]};
    *(__nv_bfloat162*)(g_Wlo + o)     = __nv_bfloat162{lo[0], lo[1]};
    *(__nv_bfloat162*)(g_Wlo + o + 2) = __nv_bfloat162{lo[2], lo[3]};
}

// ---------------------------------------------------------------------------
// Kernel: transpose edge_attr [E, L] fp32 -> [L, E] bf16 hi/lo
// ---------------------------------------------------------------------------
__global__ __launch_bounds__(256)
void conv_at_kernel(const float* __restrict__ A) {
    __shared__ float tl[32][33];
    int tx = threadIdx.x & 31, ty = threadIdx.x >> 5;
    int ls = blockIdx.x * 32;
    int ks = blockIdx.y * 32;
    #pragma unroll
    for (int i = 0; i < 4; i++)
        tl[ty + i * 8][tx] = A[(size_t)(ks + ty + i * 8) * LDIM + ls + tx];
    __syncthreads();
    #pragma unroll
    for (int i = 0; i < 4; i++) {
        float v = tl[tx][ty + i * 8];
        int l = ls + ty + i * 8;
        size_t o = (size_t)l * EDIM + ks + tx;
        __nv_bfloat16 h = __float2bfloat16(v);
        g_Ahi[o] = h;
        g_Alo[o] = __float2bfloat16(v - __bfloat162float(h));
    }
}

// ---------------------------------------------------------------------------
// Kernel: split-K bf16 HMMA GEMM with hi/lo compensation
//   partial[z][c][l] = Wh·Ah + Wh·Al + Wl·Ah over k slice z
//   grid = (LDIM/BN, MPAD/BM, KSPLIT) = (16, 2, 8) = 256 CTAs; 2 CTAs/SM
//   8 warps: 4m x 2n; warp tile 32m x 32n
// ---------------------------------------------------------------------------
__global__ __launch_bounds__(256, 2)
void gemm_kernel() {
    extern __shared__ char dsm[];
    uint32_t raw = smem_u32(dsm);
    uint32_t tb = (raw + 1023) & ~1023u;        // 1024-aligned

    const int t = threadIdx.x;
    const int wid = t >> 5;
    const int lane = t & 31;
    const int warp_m = wid & 3;                 // 0..3 -> 32-row strip
    const int warp_n = wid >> 2;                // 0..1 -> 32-col strip
    const int n0 = blockIdx.x * BN;
    const int m0 = blockIdx.y * BM;
    const int z = blockIdx.z;
    const int k_base = z * KSLICE;

    const __nv_bfloat16* pWh = g_Whi + (size_t)m0 * EDIM;
    const __nv_bfloat16* pWl = g_Wlo + (size_t)m0 * EDIM;
    const __nv_bfloat16* pAh = g_Ahi + (size_t)n0 * EDIM;
    const __nv_bfloat16* pAl = g_Alo + (size_t)n0 * EDIM;

    // ---- async load of one chunk into a stage ----
    auto load_chunk = [&](int ch, int stage) {
        uint32_t sb = tb + stage * STAGE_BYTES;
        int k0 = k_base + ch * BK;
        // W tiles: 128 rows x 8 granules = 1024 granules each
        #pragma unroll
        for (int i = 0; i < 4; i++) {
            int idx = t + i * 256;
            int r = idx >> 3, g = idx & 7;
            uint32_t so = SW128((uint32_t)(r * 128 + g * 16));
            size_t go = (size_t)r * EDIM + k0 + g * 8;
            CP_ASYNC16(sb + so, pWh + go);
            CP_ASYNC16(sb + TILE_W_BYTES + so, pWl + go);
        }
        // A tiles: 64 rows x 8 granules = 512 granules each
        #pragma unroll
        for (int i = 0; i < 2; i++) {
            int idx = t + i * 256;
            int r = idx >> 3, g = idx & 7;
            uint32_t so = SW128((uint32_t)(r * 128 + g * 16));
            size_t go = (size_t)r * EDIM + k0 + g * 8;
            CP_ASYNC16(sb + 2 * TILE_W_BYTES + so, pAh + go);
            CP_ASYNC16(sb + 2 * TILE_W_BYTES + TILE_A_BYTES + so, pAl + go);
        }
    };

    float acc[2][4][4];
    #pragma unroll
    for (int mt = 0; mt < 2; mt++)
        #pragma unroll
        for (int nt = 0; nt < 4; nt++)
            #pragma unroll
            for (int i = 0; i < 4; i++) acc[mt][nt][i] = 0.0f;

    load_chunk(0, 0);
    CP_COMMIT();

    // ldmatrix address components (constant across chunks)
    const int a_row  = warp_m * 32 + (lane & 15);     // + mt*16
    const int a_kh   = (lane >> 4) * 16;              // k-half byte offset
    const int b_row  = warp_n * 32 + ((lane >> 4) & 1) * 8 + (lane & 7);  // + np*16
    const int b_kh   = ((lane >> 3) & 1) * 16;

    for (int ch = 0; ch < NCHUNK; ch++) {
        if (ch + 1 < NCHUNK) {
            load_chunk(ch + 1, (ch + 1) & 1);
            CP_COMMIT();
            CP_WAIT(1);
        } else {
            CP_WAIT(0);
        }
        __syncthreads();

        uint32_t sb = tb + (ch & 1) * STAGE_BYTES;
        uint32_t sWh = sb, sWl = sb + TILE_W_BYTES;
        uint32_t sAh = sb + 2 * TILE_W_BYTES, sAl = sAh + TILE_A_BYTES;

        #pragma unroll
        for (int ks = 0; ks < 4; ks++) {              // 4 k16 steps per BK=64
            const int kb = ks * 32;
            uint32_t aWh[2][4], aWl[2][4], bAh[4][2], bAl[4][2];
            #pragma unroll
            for (int mt = 0; mt < 2; mt++) {
                uint32_t ad = sWh + SW128((uint32_t)((a_row + mt * 16) * 128 + kb + a_kh));
                LDM_X4(aWh[mt][0], aWh[mt][1], aWh[mt][2], aWh[mt][3], ad);
            }
            #pragma unroll
            for (int np = 0; np < 2; np++) {
                uint32_t ad = sAh + SW128((uint32_t)((b_row + np * 16) * 128 + kb + b_kh));
                uint32_t r0, r1, r2, r3;
                LDM_X4(r0, r1, r2, r3, ad);
                bAh[np * 2][0] = r0; bAh[np * 2][1] = r1;
                bAh[np * 2 + 1][0] = r2; bAh[np * 2 + 1][1] = r3;
            }
            // pass 1: Wh x Ah
            #pragma unroll
            for (int mt = 0; mt < 2; mt++)
                #pragma unroll
                for (int nt = 0; nt < 4; nt++)
                    mma16816(acc[mt][nt], aWh[mt], bAh[nt]);
            // pass 2: Wh x Al
            #pragma unroll
            for (int np = 0; np < 2; np++) {
                uint32_t ad = sAl + SW128((uint32_t)((b_row + np * 16) * 128 + kb + b_kh));
                uint32_t r0, r1, r2, r3;
                LDM_X4(r0, r1, r2, r3, ad);
                bAl[np * 2][0] = r0; bAl[np * 2][1] = r1;
                bAl[np * 2 + 1][0] = r2; bAl[np * 2 + 1][1] = r3;
            }
            #pragma unroll
            for (int mt = 0; mt < 2; mt++)
                #pragma unroll
                for (int nt = 0; nt < 4; nt++)
                    mma16816(acc[mt][nt], aWh[mt], bAl[nt]);
            // pass 3: Wl x Ah
            #pragma unroll
            for (int mt = 0; mt < 2; mt++) {
                uint32_t ad = sWl + SW128((uint32_t)((a_row + mt * 16) * 128 + kb + a_kh));
                LDM_X4(aWl[mt][0], aWl[mt][1], aWl[mt][2], aWl[mt][3], ad);
            }
            #pragma unroll
            for (int mt = 0; mt < 2; mt++)
                #pragma unroll
                for (int nt = 0; nt < 4; nt++)
                    mma16816(acc[mt][nt], aWl[mt], bAh[nt]);
        }
        __syncthreads();
    }

    // ---- epilogue: acc -> g_partial ----
    const int er = lane >> 2;            // 0..7
    const int ec = (lane & 3) * 2;
    #pragma unroll
    for (int mt = 0; mt < 2; mt++) {
        #pragma unroll
        for (int nt = 0; nt < 4; nt++) {
            int row = m0 + warp_m * 32 + mt * 16 + er;
            int col = n0 + warp_n * 32 + nt * 8 + ec;
            float* p0 = g_partial + ((size_t)z * MPAD + row) * LDIM + col;
            float* p1 = g_partial + ((size_t)z * MPAD + row + 8) * LDIM + col;
            *(float2*)p0 = make_float2(acc[mt][nt][0], acc[mt][nt][1]);
            *(float2*)p1 = make_float2(acc[mt][nt][2], acc[mt][nt][3]);
        }
    }
}

// ---------------------------------------------------------------------------
// Kernel: reduce stage 1 — grid (32 l-blocks, 16 c-groups), 256 threads.
//   For its 15 c-rows x 32 l-cols: sum 8 K-split partials, +bias, ReLU,
//   accumulate (sum e) and (sum w4*e) -> g_red1/g_red2[cg][l].
// ---------------------------------------------------------------------------
__global__ __launch_bounds__(256)
void reduce1_kernel(const float* __restrict__ b3, const float* __restrict__ w4) {
    __shared__ float red1[8][32];
    __shared__ float red2[8][32];
    const int lane = threadIdx.x & 31;
    const int w = threadIdx.x >> 5;
    const int l = blockIdx.x * 32 + lane;
    const int cg = blockIdx.y;
    const int c_lo = cg * CPG;

    float v1 = 0.0f, v2 = 0.0f;
    for (int c = c_lo + w; c < c_lo + CPG; c += 8) {
        float s = 0.0f;
        #pragma unroll
        for (int zz = 0; zz < KSPLIT; zz++)
            s += g_partial[((size_t)zz * MPAD + c) * LDIM + l];
        float e = fmaxf(s + b3[c], 0.0f);
        v1 += e;
        v2 = fmaf(w4[c], e, v2);
    }
    red1[w][lane] = v1;
    red2[w][lane] = v2;
    __syncthreads();
    if (w == 0) {
        float s1 = 0.0f, s2 = 0.0f;
        #pragma unroll
        for (int i = 0; i < 8; i++) { s1 += red1[i][lane]; s2 += red2[i][lane]; }
        g_red1[cg * LDIM + l] = s1;
        g_red2[cg * LDIM + l] = s2;
    }
}

// ---------------------------------------------------------------------------
// Kernel: reduce stage 2 — fold 16 c-groups, sigmoid, final colsum. 4 blocks.
// ---------------------------------------------------------------------------
__global__ __launch_bounds__(256)
void reduce2_kernel(const float* __restrict__ b4) {
    const int l = blockIdx.x * 256 + threadIdx.x;
    float s1 = 0.0f, s2 = 0.0f;
    #pragma unroll
    for (int cg = 0; cg < NCG; cg++) {
        s1 += g_red1[cg * LDIM + l];
        s2 += g_red2[cg * LDIM + l];
    }
    float mask = 1.0f / (1.0f + __expf(-(s2 + b4[0])));
    g_colsum[l] = s1 * (1.0f + mask) * (1.0f / (float)LDIM);
}

// ---------------------------------------------------------------------------
// Kernel: broadcast colsum[L] to out[NODES, L]
// ---------------------------------------------------------------------------
__global__ __launch_bounds__(256)
void bcast_kernel(float4* __restrict__ out, long total4) {
    __shared__ float4 cs[LDIM / 4];
    cs[threadIdx.x] = ((const float4*)g_colsum)[threadIdx.x];
    __syncthreads();
    for (long i = (long)blockIdx.x * 256 + threadIdx.x; i < total4;
         i += (long)gridDim.x * 256) {
        out[i] = cs[i & (LDIM / 4 - 1)];
    }
}

// ---------------------------------------------------------------------------
// inputs: 0=x (unused), 1=edge_index (unused), 2=edge_attr [E,L],
//         3=conv3_w [C2,E], 4=conv3_b [C2], 5=conv4_w [C2], 6=conv4_b [1]
// ---------------------------------------------------------------------------
extern "C" void kernel_launch(void* const* d_in, const int* in_sizes, int n_in,
                              void* d_out, int out_size) {
    const float* edge_attr = (const float*)d_in[2];
    const float* w3 = (const float*)d_in[3];
    const float* b3 = (const float*)d_in[4];
    const float* w4 = (const float*)d_in[5];
    const float* b4 = (const float*)d_in[6];

    cudaFuncSetAttribute(gemm_kernel,
                         cudaFuncAttributeMaxDynamicSharedMemorySize, SMEM_REQ);

    conv_w_kernel<<<(MPAD * EDIM) / (256 * 4), 256>>>(w3);
    conv_at_kernel<<<dim3(LDIM / 32, EDIM / 32), 256>>>(edge_attr);
    gemm_kernel<<<dim3(LDIM / BN, MPAD / BM, KSPLIT), 256, SMEM_REQ>>>();
    reduce1_kernel<<<dim3(LDIM / 32, NCG), 256>>>(b3, w4);
    reduce2_kernel<<<LDIM / 256, 256>>>(b4);
    bcast_kernel<<<2048, 256>>>((float4*)d_out, (long)out_size / 4);
}

// round 17
// speedup vs baseline: 1.4195x; 1.4195x over previous
#include <cuda_runtime.h>
#include <cuda_fp16.h>
#include <cstdint>

#define C2    240
#define MPAD  256
#define LDIM  1024
#define EDIM  8192
#define BM    128
#define BN    64
#define BK    64
#define KSPLIT 8
#define KSLICE (EDIM / KSPLIT)       // 1024
#define NCHUNK (KSLICE / BK)         // 16
#define TILE_W_BYTES (128 * 128)     // 128 rows x 64 fp16 = 16384 B
#define TILE_A_BYTES (64 * 128)      // 64 rows x 64 fp16 = 8192 B
#define STAGE_BYTES (TILE_W_BYTES + TILE_A_BYTES)   // 24576
#define SMEM_REQ (1024 + 2 * STAGE_BYTES)           // ~50 KB
#define NCG    24                    // c-groups in reduce stage 1
#define CPG    (C2 / NCG)            // 10 c-rows per group

// ---------------- device scratch (16B aligned for cp.async) ----------------
__device__ __align__(256) __half g_Wh[MPAD * EDIM];
__device__ __align__(256) __half g_Ah[LDIM * EDIM];   // transposed [l, k]
__device__ float g_partial[KSPLIT * MPAD * LDIM];     // 8 MB
__device__ float g_red1[NCG * LDIM];
__device__ float g_red2[NCG * LDIM];
__device__ float g_colsum[LDIM];

// ---------------- helpers ----------------
__device__ __forceinline__ uint32_t smem_u32(const void* p) {
    uint32_t a;
    asm("{ .reg .u64 t; cvta.to.shared.u64 t, %1; cvt.u32.u64 %0, t; }" : "=r"(a) : "l"(p));
    return a;
}
#define SW128(o) ((o) ^ (((o) >> 3) & 0x70))

#define CP_ASYNC16(dst, src) \
    asm volatile("cp.async.cg.shared.global [%0], [%1], 16;" :: "r"(dst), "l"(src))
#define CP_COMMIT() asm volatile("cp.async.commit_group;" ::: "memory")
#define CP_WAIT(n)  asm volatile("cp.async.wait_group %0;" :: "n"(n) : "memory")

#define LDM_X4(r0, r1, r2, r3, a) \
    asm volatile("ldmatrix.sync.aligned.m8n8.x4.shared.b16 {%0,%1,%2,%3}, [%4];" \
                 : "=r"(r0), "=r"(r1), "=r"(r2), "=r"(r3) : "r"(a))

__device__ __forceinline__ void mma16816(float* d, const uint32_t* a, const uint32_t* b) {
    asm volatile(
        "mma.sync.aligned.m16n8k16.row.col.f32.f16.f16.f32 "
        "{%0,%1,%2,%3}, {%4,%5,%6,%7}, {%8,%9}, {%0,%1,%2,%3};"
        : "+f"(d[0]), "+f"(d[1]), "+f"(d[2]), "+f"(d[3])
        : "r"(a[0]), "r"(a[1]), "r"(a[2]), "r"(a[3]), "r"(b[0]), "r"(b[1]));
}

// ---------------------------------------------------------------------------
// Kernel: convert W fp32 -> fp16, pad rows [240,256) with zeros
// ---------------------------------------------------------------------------
__global__ __launch_bounds__(256)
void conv_w_kernel(const float* __restrict__ W) {
    int gid = blockIdx.x * 256 + threadIdx.x;
    int idx4 = gid * 4;
    int row = idx4 >> 13;
    int col = idx4 & (EDIM - 1);
    float4 v = make_float4(0.f, 0.f, 0.f, 0.f);
    if (row < C2) v = *(const float4*)(W + (size_t)row * EDIM + col);
    __half2 h01 = __halves2half2(__float2half_rn(v.x), __float2half_rn(v.y));
    __half2 h23 = __halves2half2(__float2half_rn(v.z), __float2half_rn(v.w));
    size_t o = (size_t)row * EDIM + col;
    *(__half2*)(g_Wh + o)     = h01;
    *(__half2*)(g_Wh + o + 2) = h23;
}

// ---------------------------------------------------------------------------
// Kernel: transpose edge_attr [E, L] fp32 -> [L, E] fp16
// ---------------------------------------------------------------------------
__global__ __launch_bounds__(256)
void conv_at_kernel(const float* __restrict__ A) {
    __shared__ float tl[32][33];
    int tx = threadIdx.x & 31, ty = threadIdx.x >> 5;
    int ls = blockIdx.x * 32;
    int ks = blockIdx.y * 32;
    #pragma unroll
    for (int i = 0; i < 4; i++)
        tl[ty + i * 8][tx] = A[(size_t)(ks + ty + i * 8) * LDIM + ls + tx];
    __syncthreads();
    #pragma unroll
    for (int i = 0; i < 4; i++) {
        float v = tl[tx][ty + i * 8];
        int l = ls + ty + i * 8;
        g_Ah[(size_t)l * EDIM + ks + tx] = __float2half_rn(v);
    }
}

// ---------------------------------------------------------------------------
// Kernel: split-K fp16 HMMA GEMM (single pass)
//   partial[z][c][l] = W·A over k slice z  (fp32 accumulate)
//   grid = (LDIM/BN, MPAD/BM, KSPLIT) = (16, 2, 8) = 256 CTAs; 2 CTAs/SM
//   8 warps: 4m x 2n; warp tile 32m x 32n
// ---------------------------------------------------------------------------
__global__ __launch_bounds__(256, 2)
void gemm_kernel() {
    extern __shared__ char dsm[];
    uint32_t raw = smem_u32(dsm);
    uint32_t tb = (raw + 1023) & ~1023u;        // 1024-aligned

    const int t = threadIdx.x;
    const int wid = t >> 5;
    const int lane = t & 31;
    const int warp_m = wid & 3;                 // 0..3 -> 32-row strip
    const int warp_n = wid >> 2;                // 0..1 -> 32-col strip
    const int n0 = blockIdx.x * BN;
    const int m0 = blockIdx.y * BM;
    const int z = blockIdx.z;
    const int k_base = z * KSLICE;

    const __half* pW = g_Wh + (size_t)m0 * EDIM;
    const __half* pA = g_Ah + (size_t)n0 * EDIM;

    // ---- async load of one chunk into a stage ----
    auto load_chunk = [&](int ch, int stage) {
        uint32_t sb = tb + stage * STAGE_BYTES;
        int k0 = k_base + ch * BK;
        // W tile: 128 rows x 8 granules = 1024 granules
        #pragma unroll
        for (int i = 0; i < 4; i++) {
            int idx = t + i * 256;
            int r = idx >> 3, g = idx & 7;
            uint32_t so = SW128((uint32_t)(r * 128 + g * 16));
            CP_ASYNC16(sb + so, pW + (size_t)r * EDIM + k0 + g * 8);
        }
        // A tile: 64 rows x 8 granules = 512 granules
        #pragma unroll
        for (int i = 0; i < 2; i++) {
            int idx = t + i * 256;
            int r = idx >> 3, g = idx & 7;
            uint32_t so = SW128((uint32_t)(r * 128 + g * 16));
            CP_ASYNC16(sb + TILE_W_BYTES + so, pA + (size_t)r * EDIM + k0 + g * 8);
        }
    };

    float acc[2][4][4];
    #pragma unroll
    for (int mt = 0; mt < 2; mt++)
        #pragma unroll
        for (int nt = 0; nt < 4; nt++)
            #pragma unroll
            for (int i = 0; i < 4; i++) acc[mt][nt][i] = 0.0f;

    load_chunk(0, 0);
    CP_COMMIT();

    // ldmatrix address components (constant across chunks)
    const int a_row  = warp_m * 32 + (lane & 15);     // + mt*16
    const int a_kh   = (lane >> 4) * 16;              // k-half byte offset
    const int b_row  = warp_n * 32 + ((lane >> 4) & 1) * 8 + (lane & 7);  // + np*16
    const int b_kh   = ((lane >> 3) & 1) * 16;

    for (int ch = 0; ch < NCHUNK; ch++) {
        if (ch + 1 < NCHUNK) {
            load_chunk(ch + 1, (ch + 1) & 1);
            CP_COMMIT();
            CP_WAIT(1);
        } else {
            CP_WAIT(0);
        }
        __syncthreads();

        uint32_t sb = tb + (ch & 1) * STAGE_BYTES;
        uint32_t sW = sb, sA = sb + TILE_W_BYTES;

        #pragma unroll
        for (int ks = 0; ks < 4; ks++) {              // 4 k16 steps per BK=64
            const int kb = ks * 32;
            uint32_t aW[2][4], bA[4][2];
            #pragma unroll
            for (int mt = 0; mt < 2; mt++) {
                uint32_t ad = sW + SW128((uint32_t)((a_row + mt * 16) * 128 + kb + a_kh));
                LDM_X4(aW[mt][0], aW[mt][1], aW[mt][2], aW[mt][3], ad);
            }
            #pragma unroll
            for (int np = 0; np < 2; np++) {
                uint32_t ad = sA + SW128((uint32_t)((b_row + np * 16) * 128 + kb + b_kh));
                uint32_t r0, r1, r2, r3;
                LDM_X4(r0, r1, r2, r3, ad);
                bA[np * 2][0] = r0; bA[np * 2][1] = r1;
                bA[np * 2 + 1][0] = r2; bA[np * 2 + 1][1] = r3;
            }
            #pragma unroll
            for (int mt = 0; mt < 2; mt++)
                #pragma unroll
                for (int nt = 0; nt < 4; nt++)
                    mma16816(acc[mt][nt], aW[mt], bA[nt]);
        }
        __syncthreads();
    }

    // ---- epilogue: acc -> g_partial ----
    const int er = lane >> 2;            // 0..7
    const int ec = (lane & 3) * 2;
    #pragma unroll
    for (int mt = 0; mt < 2; mt++) {
        #pragma unroll
        for (int nt = 0; nt < 4; nt++) {
            int row = m0 + warp_m * 32 + mt * 16 + er;
            int col = n0 + warp_n * 32 + nt * 8 + ec;
            float* p0 = g_partial + ((size_t)z * MPAD + row) * LDIM + col;
            float* p1 = g_partial + ((size_t)z * MPAD + row + 8) * LDIM + col;
            *(float2*)p0 = make_float2(acc[mt][nt][0], acc[mt][nt][1]);
            *(float2*)p1 = make_float2(acc[mt][nt][2], acc[mt][nt][3]);
        }
    }
}

// ---------------------------------------------------------------------------
// Kernel: reduce stage 1 — grid (32 l-blocks, 24 c-groups), 256 threads.
//   For its 10 c-rows x 32 l-cols: sum 8 K-split partials, +bias, ReLU,
//   accumulate (sum e) and (sum w4*e) -> g_red1/g_red2[cg][l].
// ---------------------------------------------------------------------------
__global__ __launch_bounds__(256)
void reduce1_kernel(const float* __restrict__ b3, const float* __restrict__ w4) {
    __shared__ float red1[8][32];
    __shared__ float red2[8][32];
    const int lane = threadIdx.x & 31;
    const int w = threadIdx.x >> 5;
    const int l = blockIdx.x * 32 + lane;
    const int cg = blockIdx.y;
    const int c_lo = cg * CPG;

    float v1 = 0.0f, v2 = 0.0f;
    for (int c = c_lo + w; c < c_lo + CPG; c += 8) {
        float s = 0.0f;
        #pragma unroll
        for (int zz = 0; zz < KSPLIT; zz++)
            s += g_partial[((size_t)zz * MPAD + c) * LDIM + l];
        float e = fmaxf(s + b3[c], 0.0f);
        v1 += e;
        v2 = fmaf(w4[c], e, v2);
    }
    red1[w][lane] = v1;
    red2[w][lane] = v2;
    __syncthreads();
    if (w == 0) {
        float s1 = 0.0f, s2 = 0.0f;
        #pragma unroll
        for (int i = 0; i < 8; i++) { s1 += red1[i][lane]; s2 += red2[i][lane]; }
        g_red1[cg * LDIM + l] = s1;
        g_red2[cg * LDIM + l] = s2;
    }
}

// ---------------------------------------------------------------------------
// Kernel: reduce stage 2 — fold 24 c-groups, sigmoid, final colsum. 4 blocks.
// ---------------------------------------------------------------------------
__global__ __launch_bounds__(256)
void reduce2_kernel(const float* __restrict__ b4) {
    const int l = blockIdx.x * 256 + threadIdx.x;
    float s1 = 0.0f, s2 = 0.0f;
    #pragma unroll
    for (int cg = 0; cg < NCG; cg++) {
        s1 += g_red1[cg * LDIM + l];
        s2 += g_red2[cg * LDIM + l];
    }
    float mask = 1.0f / (1.0f + __expf(-(s2 + b4[0])));
    g_colsum[l] = s1 * (1.0f + mask) * (1.0f / (float)LDIM);
}

// ---------------------------------------------------------------------------
// Kernel: broadcast colsum[L] to out[NODES, L]
// ---------------------------------------------------------------------------
__global__ __launch_bounds__(256)
void bcast_kernel(float4* __restrict__ out, long total4) {
    __shared__ float4 cs[LDIM / 4];
    cs[threadIdx.x] = ((const float4*)g_colsum)[threadIdx.x];
    __syncthreads();
    for (long i = (long)blockIdx.x * 256 + threadIdx.x; i < total4;
         i += (long)gridDim.x * 256) {
        out[i] = cs[i & (LDIM / 4 - 1)];
    }
}

// ---------------------------------------------------------------------------
// inputs: 0=x (unused), 1=edge_index (unused), 2=edge_attr [E,L],
//         3=conv3_w [C2,E], 4=conv3_b [C2], 5=conv4_w [C2], 6=conv4_b [1]
// ---------------------------------------------------------------------------
extern "C" void kernel_launch(void* const* d_in, const int* in_sizes, int n_in,
                              void* d_out, int out_size) {
    const float* edge_attr = (const float*)d_in[2];
    const float* w3 = (const float*)d_in[3];
    const float* b3 = (const float*)d_in[4];
    const float* w4 = (const float*)d_in[5];
    const float* b4 = (const float*)d_in[6];

    cudaFuncSetAttribute(gemm_kernel,
                         cudaFuncAttributeMaxDynamicSharedMemorySize, SMEM_REQ);

    conv_w_kernel<<<(MPAD * EDIM) / (256 * 4), 256>>>(w3);
    conv_at_kernel<<<dim3(LDIM / 32, EDIM / 32), 256>>>(edge_attr);
    gemm_kernel<<<dim3(LDIM / BN, MPAD / BM, KSPLIT), 256, SMEM_REQ>>>();
    reduce1_kernel<<<dim3(LDIM / 32, NCG), 256>>>(b3, w4);
    reduce2_kernel<<<LDIM / 256, 256>>>(b4);
    bcast_kernel<<<2048, 256>>>((float4*)d_out, (long)out_size / 4);
}